// round 2
// baseline (speedup 1.0000x reference)
#include <cuda_runtime.h>

// Trilinear spatial-transformer sampler with degenerate depth axis.
// Output (1,64,64,32). Grid point (oy,ox,k) contributes only when its
// transformed z lands in [31,33) (image slab at depth 32 of the padded
// 65-deep volume). z is linear in k -> analytic active-k window.
//
// R2: float4 per thread (8 threads/pixel, warp = 4 adjacent pixels).
//   - 4x fewer warp instructions for scalar math
//   - LDG.128 gathers (each 8-lane group = one contiguous 128B corner line)
//   - 4 independent FMA accumulator chains per thread (ILP)
//   - warp-union k-window via redux.sync, exact per-lane band test inside
//
// Faithful semantics: trunc-toward-zero int casts, clip-then-weight,
// reference's x/y swap (fx pairs with the row index).

__global__ __launch_bounds__(64) void stn4_kernel(
    const float4* __restrict__ img,  // (128,128,8) float4  == (128,128,32) f32
    const float*  __restrict__ T,    // 12 floats, row-major 3x4
    float4*       __restrict__ out)  // (64,64,8) float4
{
    int t   = blockIdx.x * 64 + threadIdx.x;   // 32768 threads
    int cg  = t & 7;                            // channel group (float4)
    int pix = t >> 3;
    int ox  = pix & 63;
    int oy  = (pix >> 6) & 63;

    float xg = fmaf((float)ox, 2.0f / 63.0f, -1.0f);
    float yg = fmaf((float)oy, 2.0f / 63.0f, -1.0f);

    float t0  = __ldg(T + 0),  t1  = __ldg(T + 1),  t2  = __ldg(T + 2),  t3  = __ldg(T + 3);
    float t4  = __ldg(T + 4),  t5  = __ldg(T + 5),  t6  = __ldg(T + 6),  t7  = __ldg(T + 7);
    float t8  = __ldg(T + 8),  t9  = __ldg(T + 9),  t10 = __ldg(T + 10), t11 = __ldg(T + 11);

    // per-pixel base of each transformed coordinate (zg term added per-k)
    float bx = fmaf(t0, xg, fmaf(t1, yg, t3));
    float by = fmaf(t4, xg, fmaf(t5, yg, t7));
    float bz = fmaf(t8, xg, fmaf(t9, yg, t11));

    // Analytic active-k window: z(k) = C + D*k, want z in [31,33).
    float C = 32.5f * (bz + 1.0f - t10);
    float D = t10 * (65.0f / 64.0f);

    int kLo = 0, kHi = 64;
    if (fabsf(D) > 1e-6f) {
        float invD = __frcp_rn(D);
        float k1 = (31.0f - C) * invD;
        float k2 = (33.0f - C) * invD;
        float lo = fminf(k1, k2), hi = fmaxf(k1, k2);
        lo = fminf(fmaxf(lo, -4.0f), 68.0f);
        hi = fminf(fmaxf(hi, -4.0f), 68.0f);
        kLo = max(0,  (int)floorf(lo) - 2);
        kHi = min(64, (int)ceilf(hi)  + 2);
    } else {
        if (C < 29.0f || C > 35.0f) { kHi = -1; }
    }

    // Warp-union loop bounds (adjacent pixels -> nearly identical windows).
    kLo = __reduce_min_sync(0xffffffffu, kLo);
    kHi = __reduce_max_sync(0xffffffffu, kHi);

    float a0 = 0.0f, a1 = 0.0f, a2 = 0.0f, a3 = 0.0f;

    #pragma unroll 4
    for (int k = kLo; k <= kHi; ++k) {
        // exact per-k band test (window is only a bound)
        float zg = fmaf((float)k, 2.0f / 64.0f, -1.0f);
        float sz = fmaf(t10, zg, bz);
        float z  = 0.5f * (sz + 1.0f) * 65.0f;
        int zt = (int)z;  // trunc toward zero
        if (zt == 31 || zt == 32) {
            // z0=clip(zt)=32 pairs with fz0 = 33-z (zt==32)
            // z1=clip(zt+1)=32 pairs with fz1 = z-31 (zt==31)
            float zw = (zt == 32) ? (33.0f - z) : (z - 31.0f);

            float sx = fmaf(t2, zg, bx);
            float sy = fmaf(t6, zg, by);
            float x = 0.5f * (sx + 1.0f) * 128.0f;
            float y = 0.5f * (sy + 1.0f) * 128.0f;

            int xi = (int)x;   // trunc
            int yi = (int)y;
            int x0 = min(max(xi,     0), 127);
            int x1 = min(max(xi + 1, 0), 127);
            int y0 = min(max(yi,     0), 127);
            int y1 = min(max(yi + 1, 0), 127);

            float fx0 = (float)x1 - x;
            float fx1 = x - (float)x0;
            float fy0 = (float)y1 - y;
            float fy1 = y - (float)y0;

            // x/y swap: fx pairs with row (y) index, fy with col (x) index
            float4 v00 = __ldg(img + ((y0 << 7) + x0) * 8 + cg);  // fx0*fy0
            float4 v01 = __ldg(img + ((y0 << 7) + x1) * 8 + cg);  // fx0*fy1
            float4 v10 = __ldg(img + ((y1 << 7) + x0) * 8 + cg);  // fx1*fy0
            float4 v11 = __ldg(img + ((y1 << 7) + x1) * 8 + cg);  // fx1*fy1

            float w00 = fx0 * fy0, w01 = fx0 * fy1;
            float w10 = fx1 * fy0, w11 = fx1 * fy1;

            a0 = fmaf(zw, fmaf(w00, v00.x, fmaf(w01, v01.x, fmaf(w10, v10.x, w11 * v11.x))), a0);
            a1 = fmaf(zw, fmaf(w00, v00.y, fmaf(w01, v01.y, fmaf(w10, v10.y, w11 * v11.y))), a1);
            a2 = fmaf(zw, fmaf(w00, v00.z, fmaf(w01, v01.z, fmaf(w10, v10.z, w11 * v11.z))), a2);
            a3 = fmaf(zw, fmaf(w00, v00.w, fmaf(w01, v01.w, fmaf(w10, v10.w, w11 * v11.w))), a3);
        }
    }

    float4 r; r.x = a0; r.y = a1; r.z = a2; r.w = a3;
    out[t] = r;
}

extern "C" void kernel_launch(void* const* d_in, const int* in_sizes, int n_in,
                              void* d_out, int out_size)
{
    const float4* img = (const float4*)d_in[0];  // (1,128,128,32) f32
    const float*  T   = (const float*)d_in[1];   // (1,12) f32
    float4* out       = (float4*)d_out;          // (1,64,64,32) f32

    // 32768 threads: 8 threads (float4 channel groups) per output pixel
    stn4_kernel<<<512, 64>>>(img, T, out);
}

// round 3
// speedup vs baseline: 1.5761x; 1.5761x over previous
#include <cuda_runtime.h>

// Trilinear spatial-transformer sampler, degenerate depth axis.
// Output (1,64,64,32). Grid point (oy,ox,k) contributes only when its
// transformed z lands in [31,33) (image slab at depth 32 of the padded
// 65-deep volume).
//
// R3: warp per pixel, two phases.
//   Phase 1 (lane = k): scan all 65 k in <=3 warp chunks; compute band
//     test + zw-folded bilinear weights + packed corner offsets; ballot-
//     compact active entries into shared memory. Kills the 32x lane-
//     redundant coordinate math of the naive layout.
//   Phase 2 (lane = channel): iterate compacted entries; 2 broadcast
//     LDS.128 + 4 coalesced LDG + 4 FMAs into 4 independent accumulators.
//
// Faithful semantics: trunc-toward-zero int casts, clip-then-weight,
// reference's x/y swap (weight fx[i] pairs with the row index ys[i]).

#define FULL 0xffffffffu
#define MAX_ENT 66   // k in [0,64] -> at most 65 active entries
#define WARPS_PER_BLOCK 8

__global__ __launch_bounds__(256) void stn_kernel(
    const float* __restrict__ img,   // (128,128,32) f32
    const float* __restrict__ T,     // 12 floats, row-major 3x4
    float* __restrict__ out)         // (64,64,32) f32
{
    // entry = 8 words: [base, dx, dy, pad, w00, w01, w10, w11]
    __shared__ float sent[WARPS_PER_BLOCK][MAX_ENT][8];

    int warpInBlk = threadIdx.x >> 5;
    int lane      = threadIdx.x & 31;
    int pix       = blockIdx.x * WARPS_PER_BLOCK + warpInBlk;  // 0..4095
    int ox        = pix & 63;
    int oy        = (pix >> 6) & 63;

    float xg = fmaf((float)ox, 2.0f / 63.0f, -1.0f);
    float yg = fmaf((float)oy, 2.0f / 63.0f, -1.0f);

    float t0  = __ldg(T + 0),  t1  = __ldg(T + 1),  t2  = __ldg(T + 2),  t3  = __ldg(T + 3);
    float t4  = __ldg(T + 4),  t5  = __ldg(T + 5),  t6  = __ldg(T + 6),  t7  = __ldg(T + 7);
    float t8  = __ldg(T + 8),  t9  = __ldg(T + 9),  t10 = __ldg(T + 10), t11 = __ldg(T + 11);

    // per-pixel base of each transformed coordinate (zg term added per-k)
    float bx = fmaf(t0, xg, fmaf(t1, yg, t3));
    float by = fmaf(t4, xg, fmaf(t5, yg, t7));
    float bz = fmaf(t8, xg, fmaf(t9, yg, t11));

    // ---------------- Phase 1: lane = k, compact active entries ----------
    int cnt = 0;
    float (*ent)[8] = sent[warpInBlk];

    #pragma unroll
    for (int ch = 0; ch < 3; ++ch) {
        int k = ch * 32 + lane;            // 0..95; valid k: 0..64
        bool act = false;
        int  base = 0, dx = 0, dy = 0;
        float w00 = 0.f, w01 = 0.f, w10 = 0.f, w11 = 0.f;

        if (k <= 64) {
            float zg = fmaf((float)k, 2.0f / 64.0f, -1.0f);
            float sz = fmaf(t10, zg, bz);
            float z  = 0.5f * (sz + 1.0f) * 65.0f;
            int zt = (int)z;                       // trunc toward zero
            if (zt == 31 || zt == 32) {
                // z0=clip(zt)=32 pairs with fz0 = 33-z (zt==32)
                // z1=clip(zt+1)=32 pairs with fz1 = z-31 (zt==31)
                float zw = (zt == 32) ? (33.0f - z) : (z - 31.0f);

                float sx = fmaf(t2, zg, bx);
                float sy = fmaf(t6, zg, by);
                float x = 0.5f * (sx + 1.0f) * 128.0f;
                float y = 0.5f * (sy + 1.0f) * 128.0f;

                int xi = (int)x;                   // trunc
                int yi = (int)y;
                int x0 = min(max(xi,     0), 127);
                int x1 = min(max(xi + 1, 0), 127);
                int y0 = min(max(yi,     0), 127);
                int y1 = min(max(yi + 1, 0), 127);

                // weights from CLIPPED corner coords (faithful to reference)
                float fx0 = (float)x1 - x;
                float fx1 = x - (float)x0;
                float fy0 = (float)y1 - y;
                float fy1 = y - (float)y0;

                // x/y swap: fx pairs with row (y) index, fy with col (x)
                w00 = zw * fx0 * fy0;   // (y0, x0)
                w01 = zw * fx0 * fy1;   // (y0, x1)
                w10 = zw * fx1 * fy0;   // (y1, x0)
                w11 = zw * fx1 * fy1;   // (y1, x1)

                base = ((y0 << 7) + x0) << 5;      // float offset of (y0,x0,ch0)
                dx   = (x1 - x0) << 5;             // 0 or 32
                dy   = (y1 - y0) << 12;            // 0 or 4096
                act  = true;
            }
        }

        unsigned m  = __ballot_sync(FULL, act);
        int pos = cnt + __popc(m & ((1u << lane) - 1u));
        if (act) {
            float* e = ent[pos];
            e[0] = __int_as_float(base);
            e[1] = __int_as_float(dx);
            e[2] = __int_as_float(dy);
            e[4] = w00; e[5] = w01; e[6] = w10; e[7] = w11;
        }
        cnt += __popc(m);
    }

    __syncwarp();

    // ---------------- Phase 2: lane = channel, gather + accumulate -------
    const float* imgc = img + lane;
    float a00 = 0.f, a01 = 0.f, a10 = 0.f, a11 = 0.f;

    #pragma unroll 2
    for (int e = 0; e < cnt; ++e) {
        float4 hdr = *(const float4*)&ent[e][0];   // broadcast LDS.128
        float4 w   = *(const float4*)&ent[e][4];   // broadcast LDS.128
        int base = __float_as_int(hdr.x);
        int dx   = __float_as_int(hdr.y);
        int dy   = __float_as_int(hdr.z);

        float v00 = __ldg(imgc + base);
        float v01 = __ldg(imgc + base + dx);
        float v10 = __ldg(imgc + base + dy);
        float v11 = __ldg(imgc + base + dx + dy);

        a00 = fmaf(w.x, v00, a00);
        a01 = fmaf(w.y, v01, a01);
        a10 = fmaf(w.z, v10, a10);
        a11 = fmaf(w.w, v11, a11);
    }

    out[(pix << 5) + lane] = (a00 + a01) + (a10 + a11);
}

extern "C" void kernel_launch(void* const* d_in, const int* in_sizes, int n_in,
                              void* d_out, int out_size)
{
    const float* img = (const float*)d_in[0];   // (1,128,128,32) f32
    const float* T   = (const float*)d_in[1];   // (1,12) f32
    float* out       = (float*)d_out;           // (1,64,64,32) f32

    // warp per pixel: 4096 warps = 512 blocks x 256 threads
    stn_kernel<<<512, 256>>>(img, T, out);
}

// round 4
// speedup vs baseline: 1.8857x; 1.1964x over previous
#include <cuda_runtime.h>

// Trilinear spatial-transformer sampler, degenerate depth axis.
// Output (1,64,64,32). Grid point (oy,ox,k) contributes only when its
// transformed z lands in [31,33) (image slab at depth 32 of the padded
// 65-deep volume). z is linear in k -> analytic active-k window.
//
// R4: 4 warps per pixel (16384 warps total) for latency hiding.
//   Phase 1 (lane = k): analytic k-window; if it fits in 32 k's (typical)
//     a single warp chunk computes band test + zw-folded bilinear weights
//     + packed corner offsets, ballot-compacted into smem. Exact 3-chunk
//     scan fallback for wide windows. All 4 warps of a pixel write
//     identical entries (benign identical-value races, no sync needed).
//   Phase 2 (lane = channel): each warp handles every 4th entry:
//     2 broadcast LDS.128 + 4 coalesced LDG + 4 FMAs.
//   Combine: partials through smem + one __syncthreads.
//
// Faithful semantics: trunc-toward-zero int casts, clip-then-weight,
// reference's x/y swap (weight fx[i] pairs with the row index ys[i]).

#define FULL 0xffffffffu
#define MAX_ENT 66   // k in [0,64] -> at most 65 active entries

__global__ __launch_bounds__(256) void stn_kernel(
    const float* __restrict__ img,   // (128,128,32) f32
    const float* __restrict__ T,     // 12 floats, row-major 3x4
    float* __restrict__ out)         // (64,64,32) f32
{
    // entry = 8 words: [base, dx, dy, pad, w00, w01, w10, w11]
    __shared__ float sent[2][MAX_ENT][8];
    __shared__ float spart[2][4][32];

    int warp = threadIdx.x >> 5;
    int lane = threadIdx.x & 31;
    int pg   = warp >> 2;                  // pixel slot in block (0..1)
    int wsub = warp & 3;                   // sub-warp within pixel group
    int pix  = blockIdx.x * 2 + pg;        // 0..4095
    int ox   = pix & 63;
    int oy   = (pix >> 6) & 63;

    float xg = fmaf((float)ox, 2.0f / 63.0f, -1.0f);
    float yg = fmaf((float)oy, 2.0f / 63.0f, -1.0f);

    float t0  = __ldg(T + 0),  t1  = __ldg(T + 1),  t2  = __ldg(T + 2),  t3  = __ldg(T + 3);
    float t4  = __ldg(T + 4),  t5  = __ldg(T + 5),  t6  = __ldg(T + 6),  t7  = __ldg(T + 7);
    float t8  = __ldg(T + 8),  t9  = __ldg(T + 9),  t10 = __ldg(T + 10), t11 = __ldg(T + 11);

    // per-pixel base of each transformed coordinate (zg term added per-k)
    float bx = fmaf(t0, xg, fmaf(t1, yg, t3));
    float by = fmaf(t4, xg, fmaf(t5, yg, t7));
    float bz = fmaf(t8, xg, fmaf(t9, yg, t11));

    // Analytic active-k window: z(k) = C + D*k, want z in [31,33).
    float C = 32.5f * (bz + 1.0f - t10);
    float D = t10 * (65.0f / 64.0f);

    int kLo = 0, kHi = 64;
    if (fabsf(D) > 1e-6f) {
        float invD = __frcp_rn(D);
        float k1 = (31.0f - C) * invD;
        float k2 = (33.0f - C) * invD;
        float lo = fminf(k1, k2), hi = fmaxf(k1, k2);
        lo = fminf(fmaxf(lo, -4.0f), 68.0f);
        hi = fminf(fmaxf(hi, -4.0f), 68.0f);
        kLo = max(0,  (int)floorf(lo) - 2);
        kHi = min(64, (int)ceilf(hi)  + 2);
    } else {
        if (C < 29.0f || C > 35.0f) { kHi = -1; }  // empty
    }

    // ---------------- Phase 1: lane = k, compact active entries ----------
    int cnt = 0;
    float (*ent)[8] = sent[pg];

    int nChunks = (kHi - kLo <= 31) ? 1 : 3;
    int kBase   = (nChunks == 1) ? kLo : 0;

    for (int ch = 0; ch < nChunks; ++ch) {
        int k = kBase + ch * 32 + lane;
        bool act = false;
        int  base = 0, dx = 0, dy = 0;
        float w00 = 0.f, w01 = 0.f, w10 = 0.f, w11 = 0.f;

        if (k <= 64 && k <= kHi) {
            float zg = fmaf((float)k, 2.0f / 64.0f, -1.0f);
            float sz = fmaf(t10, zg, bz);
            float z  = 0.5f * (sz + 1.0f) * 65.0f;
            int zt = (int)z;                       // trunc toward zero
            if (zt == 31 || zt == 32) {
                // z0=clip(zt)=32 pairs with fz0 = 33-z (zt==32)
                // z1=clip(zt+1)=32 pairs with fz1 = z-31 (zt==31)
                float zw = (zt == 32) ? (33.0f - z) : (z - 31.0f);

                float sx = fmaf(t2, zg, bx);
                float sy = fmaf(t6, zg, by);
                float x = 0.5f * (sx + 1.0f) * 128.0f;
                float y = 0.5f * (sy + 1.0f) * 128.0f;

                int xi = (int)x;                   // trunc
                int yi = (int)y;
                int x0 = min(max(xi,     0), 127);
                int x1 = min(max(xi + 1, 0), 127);
                int y0 = min(max(yi,     0), 127);
                int y1 = min(max(yi + 1, 0), 127);

                // weights from CLIPPED corner coords (faithful to reference)
                float fx0 = (float)x1 - x;
                float fx1 = x - (float)x0;
                float fy0 = (float)y1 - y;
                float fy1 = y - (float)y0;

                // x/y swap: fx pairs with row (y) index, fy with col (x)
                w00 = zw * fx0 * fy0;   // (y0, x0)
                w01 = zw * fx0 * fy1;   // (y0, x1)
                w10 = zw * fx1 * fy0;   // (y1, x0)
                w11 = zw * fx1 * fy1;   // (y1, x1)

                base = ((y0 << 7) + x0) << 5;      // float offset of (y0,x0,c0)
                dx   = (x1 - x0) << 5;             // 0 or 32
                dy   = (y1 - y0) << 12;            // 0 or 4096
                act  = true;
            }
        }

        unsigned m = __ballot_sync(FULL, act);
        int pos = cnt + __popc(m & ((1u << lane) - 1u));
        if (act) {
            float* e = ent[pos];
            e[0] = __int_as_float(base);
            e[1] = __int_as_float(dx);
            e[2] = __int_as_float(dy);
            e[4] = w00; e[5] = w01; e[6] = w10; e[7] = w11;
        }
        cnt += __popc(m);
    }

    __syncwarp();

    // ---------------- Phase 2: lane = channel, every 4th entry -----------
    const float* imgc = img + lane;
    float a00 = 0.f, a01 = 0.f, a10 = 0.f, a11 = 0.f;

    for (int e = wsub; e < cnt; e += 4) {
        float4 hdr = *(const float4*)&ent[e][0];   // broadcast LDS.128
        float4 w   = *(const float4*)&ent[e][4];   // broadcast LDS.128
        int base = __float_as_int(hdr.x);
        int dx   = __float_as_int(hdr.y);
        int dy   = __float_as_int(hdr.z);

        float v00 = __ldg(imgc + base);
        float v01 = __ldg(imgc + base + dx);
        float v10 = __ldg(imgc + base + dy);
        float v11 = __ldg(imgc + base + dx + dy);

        a00 = fmaf(w.x, v00, a00);
        a01 = fmaf(w.y, v01, a01);
        a10 = fmaf(w.z, v10, a10);
        a11 = fmaf(w.w, v11, a11);
    }

    spart[pg][wsub][lane] = (a00 + a01) + (a10 + a11);
    __syncthreads();

    if (wsub == 0) {
        float r = (spart[pg][0][lane] + spart[pg][1][lane])
                + (spart[pg][2][lane] + spart[pg][3][lane]);
        out[(pix << 5) + lane] = r;
    }
}

extern "C" void kernel_launch(void* const* d_in, const int* in_sizes, int n_in,
                              void* d_out, int out_size)
{
    const float* img = (const float*)d_in[0];   // (1,128,128,32) f32
    const float* T   = (const float*)d_in[1];   // (1,12) f32
    float* out       = (float*)d_out;           // (1,64,64,32) f32

    // 4 warps per pixel: 4096 pixels * 4 = 16384 warps = 2048 blocks x 256
    stn_kernel<<<2048, 256>>>(img, T, out);
}

// round 5
// speedup vs baseline: 2.1728x; 1.1523x over previous
#include <cuda_runtime.h>

// Trilinear spatial-transformer sampler, degenerate depth axis.
// Output (1,64,64,32). Grid point (oy,ox,k) contributes only when its
// transformed z lands in [31,33) (image slab at depth 32 of the padded
// 65-deep volume). z is linear in k -> analytic active-k window.
//
// R5: 4 warps per pixel (16384 warps), but phase 1 runs on ONE warp per
//     pixel only — the other 3 warps skip the T loads, coordinate math,
//     window and compaction entirely (they were 4x redundant in R4).
//     T loaded as 3x float4. Entry carries precomputed dx+dy.
//   Phase 1 (warp 0 of pixel, lane = k): analytic k-window; single warp
//     chunk when it fits in 32 k's (typical), exact 3-chunk fallback.
//     Ballot-compacted entries + cnt into smem.
//   Phase 2 (all 4 warps, lane = channel): every 4th entry:
//     2 broadcast LDS.128 + 4 coalesced LDG + 4 FMAs.
//   Combine: partials through smem + __syncthreads.
//
// Faithful semantics: trunc-toward-zero int casts, clip-then-weight,
// reference's x/y swap (weight fx[i] pairs with the row index ys[i]).

#define FULL 0xffffffffu
#define MAX_ENT 66   // k in [0,64] -> at most 65 active entries

__global__ __launch_bounds__(256) void stn_kernel(
    const float* __restrict__ img,   // (128,128,32) f32
    const float* __restrict__ T,     // 12 floats, row-major 3x4
    float* __restrict__ out)         // (64,64,32) f32
{
    // entry = 8 words: [base, dx, dy, dxdy, w00, w01, w10, w11]
    __shared__ float sent[2][MAX_ENT][8];
    __shared__ float spart[2][4][32];
    __shared__ int   scnt[2];

    int warp = threadIdx.x >> 5;
    int lane = threadIdx.x & 31;
    int pg   = warp >> 2;                  // pixel slot in block (0..1)
    int wsub = warp & 3;                   // sub-warp within pixel group
    int pix  = blockIdx.x * 2 + pg;        // 0..4095

    // ---------------- Phase 1: one warp per pixel ------------------------
    if (wsub == 0) {
        int ox = pix & 63;
        int oy = (pix >> 6) & 63;

        float xg = fmaf((float)ox, 2.0f / 63.0f, -1.0f);
        float yg = fmaf((float)oy, 2.0f / 63.0f, -1.0f);

        const float4* T4 = (const float4*)T;
        float4 r0 = __ldg(T4 + 0);   // t0 t1 t2 t3
        float4 r1 = __ldg(T4 + 1);   // t4 t5 t6 t7
        float4 r2 = __ldg(T4 + 2);   // t8 t9 t10 t11

        // per-pixel base of each transformed coordinate (zg term per-k)
        float bx = fmaf(r0.x, xg, fmaf(r0.y, yg, r0.w));
        float by = fmaf(r1.x, xg, fmaf(r1.y, yg, r1.w));
        float bz = fmaf(r2.x, xg, fmaf(r2.y, yg, r2.w));
        float t2c = r0.z, t6c = r1.z, t10c = r2.z;

        // Analytic active-k window: z(k) = C + D*k, want z in [31,33).
        float C = 32.5f * (bz + 1.0f - t10c);
        float D = t10c * (65.0f / 64.0f);

        int kLo = 0, kHi = 64;
        if (fabsf(D) > 1e-6f) {
            float invD = __frcp_rn(D);
            float k1 = (31.0f - C) * invD;
            float k2 = (33.0f - C) * invD;
            float lo = fminf(k1, k2), hi = fmaxf(k1, k2);
            lo = fminf(fmaxf(lo, -4.0f), 68.0f);
            hi = fminf(fmaxf(hi, -4.0f), 68.0f);
            kLo = max(0,  (int)floorf(lo) - 2);
            kHi = min(64, (int)ceilf(hi)  + 2);
        } else {
            if (C < 29.0f || C > 35.0f) { kHi = -1; }  // empty
        }

        int cnt = 0;
        float (*ent)[8] = sent[pg];

        int nChunks = (kHi - kLo <= 31) ? 1 : 3;
        int kBase   = (nChunks == 1) ? kLo : 0;

        for (int ch = 0; ch < nChunks; ++ch) {
            int k = kBase + ch * 32 + lane;
            bool act = false;
            int  base = 0, dx = 0, dy = 0;
            float w00 = 0.f, w01 = 0.f, w10 = 0.f, w11 = 0.f;

            if (k <= 64 && k <= kHi) {
                float zg = fmaf((float)k, 2.0f / 64.0f, -1.0f);
                float sz = fmaf(t10c, zg, bz);
                float z  = 0.5f * (sz + 1.0f) * 65.0f;
                int zt = (int)z;                   // trunc toward zero
                if (zt == 31 || zt == 32) {
                    // z0=clip(zt)=32 pairs with fz0 = 33-z (zt==32)
                    // z1=clip(zt+1)=32 pairs with fz1 = z-31 (zt==31)
                    float zw = (zt == 32) ? (33.0f - z) : (z - 31.0f);

                    float sx = fmaf(t2c, zg, bx);
                    float sy = fmaf(t6c, zg, by);
                    float x = 0.5f * (sx + 1.0f) * 128.0f;
                    float y = 0.5f * (sy + 1.0f) * 128.0f;

                    int xi = (int)x;               // trunc
                    int yi = (int)y;
                    int x0 = min(max(xi,     0), 127);
                    int x1 = min(max(xi + 1, 0), 127);
                    int y0 = min(max(yi,     0), 127);
                    int y1 = min(max(yi + 1, 0), 127);

                    // weights from CLIPPED corners (faithful to reference)
                    float fx0 = (float)x1 - x;
                    float fx1 = x - (float)x0;
                    float fy0 = (float)y1 - y;
                    float fy1 = y - (float)y0;

                    // x/y swap: fx pairs with row (y), fy with col (x)
                    w00 = zw * fx0 * fy0;   // (y0, x0)
                    w01 = zw * fx0 * fy1;   // (y0, x1)
                    w10 = zw * fx1 * fy0;   // (y1, x0)
                    w11 = zw * fx1 * fy1;   // (y1, x1)

                    base = ((y0 << 7) + x0) << 5;  // float off of (y0,x0,c0)
                    dx   = (x1 - x0) << 5;         // 0 or 32
                    dy   = (y1 - y0) << 12;        // 0 or 4096
                    act  = true;
                }
            }

            unsigned m = __ballot_sync(FULL, act);
            int pos = cnt + __popc(m & ((1u << lane) - 1u));
            if (act) {
                float* e = ent[pos];
                e[0] = __int_as_float(base);
                e[1] = __int_as_float(dx);
                e[2] = __int_as_float(dy);
                e[3] = __int_as_float(dx + dy);
                e[4] = w00; e[5] = w01; e[6] = w10; e[7] = w11;
            }
            cnt += __popc(m);
        }

        if (lane == 0) scnt[pg] = cnt;
    }

    __syncthreads();

    // ---------------- Phase 2: all warps, every 4th entry ----------------
    int cnt = scnt[pg];
    float (*ent)[8] = sent[pg];
    const float* imgc = img + lane;

    float a00 = 0.f, a01 = 0.f, a10 = 0.f, a11 = 0.f;

    for (int e = wsub; e < cnt; e += 4) {
        float4 hdr = *(const float4*)&ent[e][0];   // broadcast LDS.128
        float4 w   = *(const float4*)&ent[e][4];   // broadcast LDS.128
        int base = __float_as_int(hdr.x);
        int dx   = __float_as_int(hdr.y);
        int dy   = __float_as_int(hdr.z);
        int dxdy = __float_as_int(hdr.w);

        float v00 = __ldg(imgc + base);
        float v01 = __ldg(imgc + base + dx);
        float v10 = __ldg(imgc + base + dy);
        float v11 = __ldg(imgc + base + dxdy);

        a00 = fmaf(w.x, v00, a00);
        a01 = fmaf(w.y, v01, a01);
        a10 = fmaf(w.z, v10, a10);
        a11 = fmaf(w.w, v11, a11);
    }

    spart[pg][wsub][lane] = (a00 + a01) + (a10 + a11);
    __syncthreads();

    if (wsub == 0) {
        float r = (spart[pg][0][lane] + spart[pg][1][lane])
                + (spart[pg][2][lane] + spart[pg][3][lane]);
        out[(pix << 5) + lane] = r;
    }
}

extern "C" void kernel_launch(void* const* d_in, const int* in_sizes, int n_in,
                              void* d_out, int out_size)
{
    const float* img = (const float*)d_in[0];   // (1,128,128,32) f32
    const float* T   = (const float*)d_in[1];   // (1,12) f32
    float* out       = (float*)d_out;           // (1,64,64,32) f32

    // 4 warps per pixel: 4096 pixels * 4 = 16384 warps = 2048 blocks x 256
    stn_kernel<<<2048, 256>>>(img, T, out);
}

// round 6
// speedup vs baseline: 2.5143x; 1.1571x over previous
#include <cuda_runtime.h>

// Trilinear spatial-transformer sampler, degenerate depth axis.
// Output (1,64,64,32). Grid point (oy,ox,k) contributes only when its
// transformed z lands in [31,33) (image slab at depth 32 of the padded
// 65-deep volume). z is linear in k -> analytic active-k window.
//
// R6: 4 fully-independent warps per pixel (16384 warps). Each warp
//     computes the (cheap) analytic window redundantly, takes its own
//     k-quarter (q = ceil(len/4) <= 17, always one ballot chunk),
//     compacts entries into its OWN smem region, __syncwarp, and runs
//     phase 2 on its own entries. No cross-warp dependency until the
//     single final partial-sum barrier. (R5's block barrier made 3/4
//     warps idle behind warp 0's serial phase 1 -- removed.)
//
// Faithful semantics: trunc-toward-zero int casts, clip-then-weight,
// reference's x/y swap (weight fx[i] pairs with the row index ys[i]).

#define FULL 0xffffffffu
#define MAX_Q 17   // ceil(65/4)

__global__ __launch_bounds__(256) void stn_kernel(
    const float* __restrict__ img,   // (128,128,32) f32
    const float* __restrict__ T,     // 12 floats, row-major 3x4
    float* __restrict__ out)         // (64,64,32) f32
{
    // entry = 8 words: [base, dx, dy, dxdy, w00, w01, w10, w11]
    __shared__ float sent[2][4][MAX_Q][8];
    __shared__ float spart[2][4][32];

    int warp = threadIdx.x >> 5;
    int lane = threadIdx.x & 31;
    int pg   = warp >> 2;                  // pixel slot in block (0..1)
    int wsub = warp & 3;                   // sub-warp within pixel group
    int pix  = blockIdx.x * 2 + pg;        // 0..4095
    int ox   = pix & 63;
    int oy   = (pix >> 6) & 63;

    float xg = fmaf((float)ox, 2.0f / 63.0f, -1.0f);
    float yg = fmaf((float)oy, 2.0f / 63.0f, -1.0f);

    const float4* T4 = (const float4*)T;
    float4 r0 = __ldg(T4 + 0);   // t0 t1 t2 t3
    float4 r1 = __ldg(T4 + 1);   // t4 t5 t6 t7
    float4 r2 = __ldg(T4 + 2);   // t8 t9 t10 t11

    // per-pixel base of each transformed coordinate (zg term added per-k)
    float bx = fmaf(r0.x, xg, fmaf(r0.y, yg, r0.w));
    float by = fmaf(r1.x, xg, fmaf(r1.y, yg, r1.w));
    float bz = fmaf(r2.x, xg, fmaf(r2.y, yg, r2.w));
    float t2c = r0.z, t6c = r1.z, t10c = r2.z;

    // Analytic active-k window: z(k) = C + D*k, want z in [31,33).
    float C = 32.5f * (bz + 1.0f - t10c);
    float D = t10c * (65.0f / 64.0f);

    int kLo = 0, kHi = 64;
    if (fabsf(D) > 1e-6f) {
        float invD = __frcp_rn(D);
        float k1 = (31.0f - C) * invD;
        float k2 = (33.0f - C) * invD;
        float lo = fminf(k1, k2), hi = fmaxf(k1, k2);
        lo = fminf(fmaxf(lo, -4.0f), 68.0f);
        hi = fminf(fmaxf(hi, -4.0f), 68.0f);
        kLo = max(0,  (int)floorf(lo) - 2);
        kHi = min(64, (int)ceilf(hi)  + 2);
    } else {
        if (C < 29.0f || C > 35.0f) { kHi = -1; }  // empty window
    }

    // ---------------- Phase 1: own k-quarter, single ballot chunk --------
    int len  = kHi - kLo + 1;            // 0..65
    int q    = (len + 3) >> 2;           // 0..17, always <= 32
    int myLo = kLo + wsub * q;
    int k    = myLo + lane;

    bool act = false;
    int  base = 0, dx = 0, dy = 0;
    float w00 = 0.f, w01 = 0.f, w10 = 0.f, w11 = 0.f;

    if (lane < q && k <= kHi && k <= 64) {
        float zg = fmaf((float)k, 2.0f / 64.0f, -1.0f);
        float sz = fmaf(t10c, zg, bz);
        float z  = 0.5f * (sz + 1.0f) * 65.0f;
        int zt = (int)z;                       // trunc toward zero
        if (zt == 31 || zt == 32) {
            // z0=clip(zt)=32 pairs with fz0 = 33-z (zt==32)
            // z1=clip(zt+1)=32 pairs with fz1 = z-31 (zt==31)
            float zw = (zt == 32) ? (33.0f - z) : (z - 31.0f);

            float sx = fmaf(t2c, zg, bx);
            float sy = fmaf(t6c, zg, by);
            float x = 0.5f * (sx + 1.0f) * 128.0f;
            float y = 0.5f * (sy + 1.0f) * 128.0f;

            int xi = (int)x;                   // trunc
            int yi = (int)y;
            int x0 = min(max(xi,     0), 127);
            int x1 = min(max(xi + 1, 0), 127);
            int y0 = min(max(yi,     0), 127);
            int y1 = min(max(yi + 1, 0), 127);

            // weights from CLIPPED corner coords (faithful to reference)
            float fx0 = (float)x1 - x;
            float fx1 = x - (float)x0;
            float fy0 = (float)y1 - y;
            float fy1 = y - (float)y0;

            // x/y swap: fx pairs with row (y) index, fy with col (x)
            w00 = zw * fx0 * fy0;   // (y0, x0)
            w01 = zw * fx0 * fy1;   // (y0, x1)
            w10 = zw * fx1 * fy0;   // (y1, x0)
            w11 = zw * fx1 * fy1;   // (y1, x1)

            base = ((y0 << 7) + x0) << 5;      // float offset of (y0,x0,c0)
            dx   = (x1 - x0) << 5;             // 0 or 32
            dy   = (y1 - y0) << 12;            // 0 or 4096
            act  = true;
        }
    }

    float (*ent)[8] = sent[pg][wsub];
    unsigned m = __ballot_sync(FULL, act);
    int cnt = __popc(m);
    if (act) {
        float* e = ent[__popc(m & ((1u << lane) - 1u))];
        float4 h; h.x = __int_as_float(base);
                  h.y = __int_as_float(dx);
                  h.z = __int_as_float(dy);
                  h.w = __int_as_float(dx + dy);
        float4 w; w.x = w00; w.y = w01; w.z = w10; w.w = w11;
        *(float4*)&e[0] = h;
        *(float4*)&e[4] = w;
    }

    __syncwarp();

    // ---------------- Phase 2: own entries, lane = channel ---------------
    const float* imgc = img + lane;
    float a00 = 0.f, a01 = 0.f, a10 = 0.f, a11 = 0.f;

    #pragma unroll 2
    for (int e = 0; e < cnt; ++e) {
        float4 hdr = *(const float4*)&ent[e][0];   // broadcast LDS.128
        float4 w   = *(const float4*)&ent[e][4];   // broadcast LDS.128
        int b    = __float_as_int(hdr.x);
        int ddx  = __float_as_int(hdr.y);
        int ddy  = __float_as_int(hdr.z);
        int ddxy = __float_as_int(hdr.w);

        float v00 = __ldg(imgc + b);
        float v01 = __ldg(imgc + b + ddx);
        float v10 = __ldg(imgc + b + ddy);
        float v11 = __ldg(imgc + b + ddxy);

        a00 = fmaf(w.x, v00, a00);
        a01 = fmaf(w.y, v01, a01);
        a10 = fmaf(w.z, v10, a10);
        a11 = fmaf(w.w, v11, a11);
    }

    spart[pg][wsub][lane] = (a00 + a01) + (a10 + a11);
    __syncthreads();

    if (wsub == 0) {
        float r = (spart[pg][0][lane] + spart[pg][1][lane])
                + (spart[pg][2][lane] + spart[pg][3][lane]);
        out[(pix << 5) + lane] = r;
    }
}

extern "C" void kernel_launch(void* const* d_in, const int* in_sizes, int n_in,
                              void* d_out, int out_size)
{
    const float* img = (const float*)d_in[0];   // (1,128,128,32) f32
    const float* T   = (const float*)d_in[1];   // (1,12) f32
    float* out       = (float*)d_out;           // (1,64,64,32) f32

    // 4 warps per pixel: 4096 pixels * 4 = 16384 warps = 2048 blocks x 256
    stn_kernel<<<2048, 256>>>(img, T, out);
}